// round 1
// baseline (speedup 1.0000x reference)
#include <cuda_runtime.h>

// ---------------- problem constants ----------------
#define D_      128
#define TWO_D   256
#define NINIT   100000
#define LVLS    64
#define MM      4096
#define NRULES  256
#define NTOT    (NINIT + LVLS * MM)   // 362144

#define EVAL_BLOCKS 1024

// ---------------- device scratch (static: no allocs allowed) ----------------
__device__ float  g_store[(size_t)NTOT * D_];           // ~185 MB embedding store
__device__ int    g_order[LVLS * MM];                   // node ids grouped by rule, per level
__device__ int    g_off[LVLS * (NRULES + 1)];           // per-level rule offsets
__device__ double g_part[EVAL_BLOCKS * 8];              // eval partial sums

// ---------------- helpers ----------------
union F2U { float2 f; unsigned long long u; };
union F4U { float4 f; unsigned long long u[2]; };

__device__ __forceinline__ void ffma2(unsigned long long& d,
                                      unsigned long long a,
                                      unsigned long long b) {
    // packed fp32x2 FMA (Blackwell FFMA2): d = a*b + d on both 32-bit halves
    asm("fma.rn.f32x2 %0, %1, %2, %0;" : "+l"(d) : "l"(a), "l"(b));
}

__device__ __forceinline__ float softplusf(float x) {
    return fmaxf(x, 0.0f) + log1pf(expf(-fabsf(x)));
}

// ---------------- 1. init embeddings ----------------
__global__ void k_init(const float* __restrict__ thax_table,
                       const float* __restrict__ sine_table,
                       const int* __restrict__ init_thax,
                       const int* __restrict__ init_sine) {
    int idx = blockIdx.x * blockDim.x + threadIdx.x;   // one float4 each
    if (idx >= NINIT * 32) return;
    int row = idx >> 5, q = idx & 31;
    int t = init_thax[row], s = init_sine[row];
    const float4 a = *(const float4*)(thax_table + (size_t)t * D_ + q * 4);
    const float4 b = *(const float4*)(sine_table + (size_t)s * D_ + q * 4);
    float4 o; o.x = a.x + b.x; o.y = a.y + b.y; o.z = a.z + b.z; o.w = a.w + b.w;
    *(float4*)(g_store + (size_t)row * D_ + q * 4) = o;
}

// ---------------- 2. bucket nodes by rule, per level ----------------
__global__ void k_group(const int* __restrict__ rules) {
    int l = blockIdx.x;
    int tid = threadIdx.x;                    // 256 threads
    __shared__ int cnt[NRULES];
    __shared__ int base[NRULES];
    cnt[tid] = 0;
    __syncthreads();
    for (int m = tid; m < MM; m += 256)
        atomicAdd(&cnt[rules[l * MM + m]], 1);
    __syncthreads();
    if (tid == 0) {
        int acc = 0;
        for (int r = 0; r < NRULES; r++) { base[r] = acc; acc += cnt[r]; }
    }
    __syncthreads();
    g_off[l * (NRULES + 1) + tid] = base[tid];
    if (tid == 0) g_off[l * (NRULES + 1) + NRULES] = MM;
    cnt[tid] = 0;
    __syncthreads();
    for (int m = tid; m < MM; m += 256) {
        int r = rules[l * MM + m];
        int pos = base[r] + atomicAdd(&cnt[r], 1);
        g_order[l * MM + pos] = m;            // order within a rule irrelevant
    }
}

// ---------------- 3. level kernel: per-rule MLP ----------------
// Block = 128 threads = 32 col-pairs x 4 node-groups, covers 64 of 128 output
// cols (half = blockIdx.x & 1). Node chunks of <=16, padded to multiple of 4;
// NN = nodes per thread (1..4), dispatched via template so accumulators stay
// in registers.
template <int NN>
__device__ __forceinline__ void level_compute(
    const float* __restrict__ Wr, unsigned long long bpk,
    int g, int cb, int nch, int out_row0,
    const float2 (*pe2)[TWO_D], const int* s_m) {

    unsigned long long acc[NN];
#pragma unroll
    for (int t = 0; t < NN; t++) acc[t] = bpk;

#pragma unroll 2
    for (int k = 0; k < TWO_D; k += 2) {
        unsigned long long w0 = *(const unsigned long long*)(Wr + (size_t)k * D_ + cb);
        unsigned long long w1 = *(const unsigned long long*)(Wr + (size_t)(k + 1) * D_ + cb);
#pragma unroll
        for (int t = 0; t < NN; t++) {
            int n = g * NN + t;
            F4U pv; pv.f = *(const float4*)&pe2[n][k];  // (vk,vk, vk+1,vk+1)
            ffma2(acc[t], w0, pv.u[0]);
            ffma2(acc[t], w1, pv.u[1]);
        }
    }
#pragma unroll
    for (int t = 0; t < NN; t++) {
        int n = g * NN + t;
        if (n < nch) {
            F2U o; o.u = acc[t];
            o.f.x = fmaxf(o.f.x, 0.0f);
            o.f.y = fmaxf(o.f.y, 0.0f);
            *(float2*)(g_store + (size_t)(out_row0 + s_m[n]) * D_ + cb) = o.f;
        }
    }
}

__global__ void __launch_bounds__(128) k_level(
    const float* __restrict__ rule_W, const float* __restrict__ rule_b,
    const int* __restrict__ parents, int lvl) {

    int r    = blockIdx.x >> 1;
    int half = blockIdx.x & 1;
    int off0 = g_off[lvl * (NRULES + 1) + r];
    int off1 = g_off[lvl * (NRULES + 1) + r + 1];
    int c = off1 - off0;
    if (c == 0) return;

    const float* Wr = rule_W + (size_t)r * TWO_D * D_;
    int tid = threadIdx.x;
    int j   = tid & 31;           // col-pair within half
    int g   = tid >> 5;           // node group 0..3
    int cb  = half * 64 + 2 * j;  // output column base

    __shared__ __align__(16) float2 pe2[16][TWO_D];   // 32 KB, values duplicated
    __shared__ int s_m[16];
    __shared__ int s_par[16][2];

    F2U bpk; bpk.f = *(const float2*)(rule_b + (size_t)r * D_ + cb);
    int out_row0 = NINIT + lvl * MM;

    for (int base = 0; base < c; base += 16) {
        int nch  = min(16, c - base);
        int pad4 = (nch + 3) & ~3;

        if (tid < 32) {
            int n = tid >> 1, w = tid & 1;
            int m = -1, p = -1;
            if (n < nch) {
                m = g_order[lvl * MM + off0 + base + n];
                p = parents[((size_t)lvl * MM + m) * 2 + w];
            }
            if (w == 0) s_m[n] = m;
            s_par[n][w] = p;
        }
        __syncthreads();

        // gather parent embeddings (concat of 2 parents = 256 values/node),
        // stored duplicated so LDS.128 yields f32x2 operands directly
        for (int i = tid; i < pad4 * 64; i += 128) {
            int n = i >> 6, q = i & 63;
            int k = q * 4;
            float4 v = make_float4(0.f, 0.f, 0.f, 0.f);
            if (n < nch) {
                int which = (k >= 128) ? 1 : 0;
                int kk = k & 127;
                int p = s_par[n][which];
                v = *(const float4*)(g_store + (size_t)p * D_ + kk);
            }
            pe2[n][k + 0] = make_float2(v.x, v.x);
            pe2[n][k + 1] = make_float2(v.y, v.y);
            pe2[n][k + 2] = make_float2(v.z, v.z);
            pe2[n][k + 3] = make_float2(v.w, v.w);
        }
        __syncthreads();

        switch (pad4 >> 2) {
            case 1: level_compute<1>(Wr, bpk.u, g, cb, nch, out_row0, pe2, s_m); break;
            case 2: level_compute<2>(Wr, bpk.u, g, cb, nch, out_row0, pe2, s_m); break;
            case 3: level_compute<3>(Wr, bpk.u, g, cb, nch, out_row0, pe2, s_m); break;
            default: level_compute<4>(Wr, bpk.u, g, cb, nch, out_row0, pe2, s_m); break;
        }
        __syncthreads();
    }
}

// ---------------- 4. eval: logits + weighted BCE, deterministic reduce ----------------
__global__ void k_eval(const float* __restrict__ eval_w,
                       const float* __restrict__ eval_b,
                       const float* __restrict__ pos_vals,
                       const float* __restrict__ neg_vals) {
    int warp = threadIdx.x >> 5, lane = threadIdx.x & 31;
    int nwarps = gridDim.x * (blockDim.x >> 5);
    int gw = blockIdx.x * (blockDim.x >> 5) + warp;

    const float4 wv = *(const float4*)(eval_w + lane * 4);
    float eb = eval_b[0];

    double s1 = 0, s2 = 0, pok = 0, nok = 0, sp = 0, sn = 0;

    for (int node = gw; node < NTOT; node += nwarps) {
        float4 x = *(const float4*)(g_store + (size_t)node * D_ + lane * 4);
        float d = x.x * wv.x + x.y * wv.y + x.z * wv.z + x.w * wv.w;
#pragma unroll
        for (int o = 16; o > 0; o >>= 1) d += __shfl_xor_sync(0xFFFFFFFFu, d, o);
        if (lane == 0) {
            float logit = d + eb;
            float p = pos_vals[node], n = neg_vals[node];
            s1 += (double)(p * softplusf(-logit));
            s2 += (double)(n * softplusf(logit));
            if (logit >= 0.0f) pok += (double)p; else nok += (double)n;
            sp += (double)p; sn += (double)n;
        }
    }

    __shared__ double sd[8][6];
    if (lane == 0) {
        sd[warp][0] = s1; sd[warp][1] = s2; sd[warp][2] = pok;
        sd[warp][3] = nok; sd[warp][4] = sp; sd[warp][5] = sn;
    }
    __syncthreads();
    if (threadIdx.x == 0) {
        double v[6] = {0, 0, 0, 0, 0, 0};
        for (int w = 0; w < 8; w++)
            for (int c2 = 0; c2 < 6; c2++) v[c2] += sd[w][c2];
        for (int c2 = 0; c2 < 6; c2++) g_part[blockIdx.x * 8 + c2] = v[c2];
    }
}

__global__ void k_final(float* __restrict__ out) {
    __shared__ double sh[6][256];
    int tid = threadIdx.x;
    double v[6] = {0, 0, 0, 0, 0, 0};
    for (int b = tid; b < EVAL_BLOCKS; b += 256)
        for (int c2 = 0; c2 < 6; c2++) v[c2] += g_part[b * 8 + c2];
    for (int c2 = 0; c2 < 6; c2++) sh[c2][tid] = v[c2];
    __syncthreads();
    for (int s = 128; s > 0; s >>= 1) {
        if (tid < s)
            for (int c2 = 0; c2 < 6; c2++) sh[c2][tid] += sh[c2][tid + s];
        __syncthreads();
    }
    if (tid == 0) {
        double S1 = sh[0][0], S2 = sh[1][0], pok = sh[2][0];
        double nok = sh[3][0], sp = sh[4][0], sn = sh[5][0];
        double pw = sn / sp;
        out[0] = (float)(pw * S1 + S2);
        out[1] = (float)pok;
        out[2] = (float)nok;
    }
}

// ---------------- launch ----------------
extern "C" void kernel_launch(void* const* d_in, const int* in_sizes, int n_in,
                              void* d_out, int out_size) {
    const float* thax_table = (const float*)d_in[0];
    const float* sine_table = (const float*)d_in[1];
    const float* rule_W     = (const float*)d_in[2];
    const float* rule_b     = (const float*)d_in[3];
    const float* eval_w     = (const float*)d_in[4];
    const float* eval_b     = (const float*)d_in[5];
    const float* pos_vals   = (const float*)d_in[6];
    const float* neg_vals   = (const float*)d_in[7];
    const int*   init_thax  = (const int*)d_in[8];
    const int*   init_sine  = (const int*)d_in[9];
    const int*   parents    = (const int*)d_in[10];
    const int*   rules      = (const int*)d_in[11];

    (void)in_sizes; (void)n_in; (void)out_size;

    k_init<<<(NINIT * 32 + 255) / 256, 256>>>(thax_table, sine_table, init_thax, init_sine);
    k_group<<<LVLS, 256>>>(rules);
    for (int l = 0; l < LVLS; l++)
        k_level<<<2 * NRULES, 128>>>(rule_W, rule_b, parents, l);
    k_eval<<<EVAL_BLOCKS, 256>>>(eval_w, eval_b, pos_vals, neg_vals);
    k_final<<<1, 256>>>((float*)d_out);
}

// round 2
// speedup vs baseline: 1.2363x; 1.2363x over previous
#include <cuda_runtime.h>

// ---------------- problem constants ----------------
#define D_      128
#define TWO_D   256
#define NINIT   100000
#define LVLS    64
#define MM      4096
#define NRULES  256
#define NTOT    (NINIT + LVLS * MM)   // 362144

#define EVAL_BLOCKS 1024
#define PF 8   // weight prefetch depth in k-pairs (distance = 16 k values)

// ---------------- device scratch (static: no allocs allowed) ----------------
__device__ float  g_store[(size_t)NTOT * D_];           // ~185 MB embedding store
__device__ int    g_order[LVLS * MM];                   // node ids grouped by rule, per level
__device__ int    g_off[LVLS * (NRULES + 1)];           // per-level rule offsets
__device__ double g_part[EVAL_BLOCKS * 8];              // eval partial sums

// ---------------- helpers ----------------
union F2U { float2 f; unsigned long long u; };
union F4U { float4 f; unsigned long long u[2]; };

__device__ __forceinline__ void ffma2(unsigned long long& d,
                                      unsigned long long a,
                                      unsigned long long b) {
    // packed fp32x2 FMA (Blackwell FFMA2): d = a*b + d on both 32-bit halves
    asm("fma.rn.f32x2 %0, %1, %2, %0;" : "+l"(d) : "l"(a), "l"(b));
}

__device__ __forceinline__ float softplusf(float x) {
    return fmaxf(x, 0.0f) + log1pf(expf(-fabsf(x)));
}

// ---------------- 1. init embeddings ----------------
__global__ void k_init(const float* __restrict__ thax_table,
                       const float* __restrict__ sine_table,
                       const int* __restrict__ init_thax,
                       const int* __restrict__ init_sine) {
    int idx = blockIdx.x * blockDim.x + threadIdx.x;   // one float4 each
    if (idx >= NINIT * 32) return;
    int row = idx >> 5, q = idx & 31;
    int t = init_thax[row], s = init_sine[row];
    const float4 a = *(const float4*)(thax_table + (size_t)t * D_ + q * 4);
    const float4 b = *(const float4*)(sine_table + (size_t)s * D_ + q * 4);
    float4 o; o.x = a.x + b.x; o.y = a.y + b.y; o.z = a.z + b.z; o.w = a.w + b.w;
    *(float4*)(g_store + (size_t)row * D_ + q * 4) = o;
}

// ---------------- 2. bucket nodes by rule, per level ----------------
__global__ void k_group(const int* __restrict__ rules) {
    int l = blockIdx.x;
    int tid = threadIdx.x;                    // 256 threads
    __shared__ int cnt[NRULES];
    __shared__ int base[NRULES];
    cnt[tid] = 0;
    __syncthreads();
    for (int m = tid; m < MM; m += 256)
        atomicAdd(&cnt[rules[l * MM + m]], 1);
    __syncthreads();
    if (tid == 0) {
        int acc = 0;
        for (int r = 0; r < NRULES; r++) { base[r] = acc; acc += cnt[r]; }
    }
    __syncthreads();
    g_off[l * (NRULES + 1) + tid] = base[tid];
    if (tid == 0) g_off[l * (NRULES + 1) + NRULES] = MM;
    cnt[tid] = 0;
    __syncthreads();
    for (int m = tid; m < MM; m += 256) {
        int r = rules[l * MM + m];
        int pos = base[r] + atomicAdd(&cnt[r], 1);
        g_order[l * MM + pos] = m;            // order within a rule irrelevant
    }
}

// ---------------- 3. level kernel: per-rule MLP ----------------
// Block = 128 threads = 32 col-pairs x 4 node-groups, covers 64 of 128 output
// cols (half = blockIdx.x & 1). Node chunks of <=16, padded to multiple of 4;
// NN = nodes per thread (1..4). Weight loads are register-pipelined PF k-pairs
// deep so the ~250-cycle L2 latency is covered by issued work, not occupancy.
template <int NN>
__device__ __forceinline__ void level_compute(
    const float* __restrict__ Wr, unsigned long long bpk,
    int g, int cb, int nch, int out_row0,
    const float2 (*pe2)[TWO_D], const int* s_m) {

    unsigned long long acc[NN];
#pragma unroll
    for (int t = 0; t < NN; t++) acc[t] = bpk;

    // prime the weight register pipeline: k-pairs 0..PF-1
    unsigned long long w0b[PF], w1b[PF];
#pragma unroll
    for (int i = 0; i < PF; i++) {
        w0b[i] = *(const unsigned long long*)(Wr + (size_t)(2 * i)     * D_ + cb);
        w1b[i] = *(const unsigned long long*)(Wr + (size_t)(2 * i + 1) * D_ + cb);
    }

#pragma unroll 1
    for (int t = 0; t < (TWO_D / 2) / PF; t++) {
#pragma unroll
        for (int i = 0; i < PF; i++) {
            int kp = t * PF + i;
            int kn = kp + PF;
            if (kn > (TWO_D / 2) - 1) kn = (TWO_D / 2) - 1;  // clamp (redundant load)
            // issue next loads FIRST (independent of current FFMAs)
            unsigned long long nw0 = *(const unsigned long long*)(Wr + (size_t)(2 * kn)     * D_ + cb);
            unsigned long long nw1 = *(const unsigned long long*)(Wr + (size_t)(2 * kn + 1) * D_ + cb);
            unsigned long long w0 = w0b[i], w1 = w1b[i];
#pragma unroll
            for (int n0 = 0; n0 < NN; n0++) {
                int n = g * NN + n0;
                F4U pv; pv.f = *(const float4*)&pe2[n][2 * kp];  // (vk,vk, vk+1,vk+1)
                ffma2(acc[n0], w0, pv.u[0]);
                ffma2(acc[n0], w1, pv.u[1]);
            }
            w0b[i] = nw0; w1b[i] = nw1;
        }
    }

#pragma unroll
    for (int t = 0; t < NN; t++) {
        int n = g * NN + t;
        if (n < nch) {
            F2U o; o.u = acc[t];
            o.f.x = fmaxf(o.f.x, 0.0f);
            o.f.y = fmaxf(o.f.y, 0.0f);
            *(float2*)(g_store + (size_t)(out_row0 + s_m[n]) * D_ + cb) = o.f;
        }
    }
}

__global__ void __launch_bounds__(128, 4) k_level(
    const float* __restrict__ rule_W, const float* __restrict__ rule_b,
    const int* __restrict__ parents, int lvl) {

    int r    = blockIdx.x >> 1;
    int half = blockIdx.x & 1;
    int off0 = g_off[lvl * (NRULES + 1) + r];
    int off1 = g_off[lvl * (NRULES + 1) + r + 1];
    int c = off1 - off0;
    if (c == 0) return;

    const float* Wr = rule_W + (size_t)r * TWO_D * D_;
    int tid = threadIdx.x;
    int j   = tid & 31;           // col-pair within half
    int g   = tid >> 5;           // node group 0..3
    int cb  = half * 64 + 2 * j;  // output column base

    __shared__ __align__(16) float2 pe2[16][TWO_D];   // 32 KB, values duplicated
    __shared__ int s_m[16];
    __shared__ int s_par[16][2];

    F2U bpk; bpk.f = *(const float2*)(rule_b + (size_t)r * D_ + cb);
    int out_row0 = NINIT + lvl * MM;

    for (int base = 0; base < c; base += 16) {
        int nch  = min(16, c - base);
        int pad4 = (nch + 3) & ~3;

        if (tid < 32) {
            int n = tid >> 1, w = tid & 1;
            int m = -1, p = -1;
            if (n < nch) {
                m = g_order[lvl * MM + off0 + base + n];
                p = parents[((size_t)lvl * MM + m) * 2 + w];
            }
            if (w == 0) s_m[n] = m;
            s_par[n][w] = p;
        }
        __syncthreads();

        // gather parent embeddings (concat of 2 parents = 256 values/node),
        // stored duplicated so LDS.128 yields f32x2 operands directly
        for (int i = tid; i < pad4 * 64; i += 128) {
            int n = i >> 6, q = i & 63;
            int k = q * 4;
            float4 v = make_float4(0.f, 0.f, 0.f, 0.f);
            if (n < nch) {
                int which = (k >= 128) ? 1 : 0;
                int kk = k & 127;
                int p = s_par[n][which];
                v = *(const float4*)(g_store + (size_t)p * D_ + kk);
            }
            pe2[n][k + 0] = make_float2(v.x, v.x);
            pe2[n][k + 1] = make_float2(v.y, v.y);
            pe2[n][k + 2] = make_float2(v.z, v.z);
            pe2[n][k + 3] = make_float2(v.w, v.w);
        }
        __syncthreads();

        switch (pad4 >> 2) {
            case 1: level_compute<1>(Wr, bpk.u, g, cb, nch, out_row0, pe2, s_m); break;
            case 2: level_compute<2>(Wr, bpk.u, g, cb, nch, out_row0, pe2, s_m); break;
            case 3: level_compute<3>(Wr, bpk.u, g, cb, nch, out_row0, pe2, s_m); break;
            default: level_compute<4>(Wr, bpk.u, g, cb, nch, out_row0, pe2, s_m); break;
        }
        __syncthreads();
    }
}

// ---------------- 4. eval: logits + weighted BCE, deterministic reduce ----------------
__global__ void k_eval(const float* __restrict__ eval_w,
                       const float* __restrict__ eval_b,
                       const float* __restrict__ pos_vals,
                       const float* __restrict__ neg_vals) {
    int warp = threadIdx.x >> 5, lane = threadIdx.x & 31;
    int nwarps = gridDim.x * (blockDim.x >> 5);
    int gw = blockIdx.x * (blockDim.x >> 5) + warp;

    const float4 wv = *(const float4*)(eval_w + lane * 4);
    float eb = eval_b[0];

    double s1 = 0, s2 = 0, pok = 0, nok = 0, sp = 0, sn = 0;

    for (int node = gw; node < NTOT; node += nwarps) {
        float4 x = *(const float4*)(g_store + (size_t)node * D_ + lane * 4);
        float d = x.x * wv.x + x.y * wv.y + x.z * wv.z + x.w * wv.w;
#pragma unroll
        for (int o = 16; o > 0; o >>= 1) d += __shfl_xor_sync(0xFFFFFFFFu, d, o);
        if (lane == 0) {
            float logit = d + eb;
            float p = pos_vals[node], n = neg_vals[node];
            s1 += (double)(p * softplusf(-logit));
            s2 += (double)(n * softplusf(logit));
            if (logit >= 0.0f) pok += (double)p; else nok += (double)n;
            sp += (double)p; sn += (double)n;
        }
    }

    __shared__ double sd[8][6];
    if (lane == 0) {
        sd[warp][0] = s1; sd[warp][1] = s2; sd[warp][2] = pok;
        sd[warp][3] = nok; sd[warp][4] = sp; sd[warp][5] = sn;
    }
    __syncthreads();
    if (threadIdx.x == 0) {
        double v[6] = {0, 0, 0, 0, 0, 0};
        for (int w = 0; w < 8; w++)
            for (int c2 = 0; c2 < 6; c2++) v[c2] += sd[w][c2];
        for (int c2 = 0; c2 < 6; c2++) g_part[blockIdx.x * 8 + c2] = v[c2];
    }
}

__global__ void k_final(float* __restrict__ out) {
    __shared__ double sh[6][256];
    int tid = threadIdx.x;
    double v[6] = {0, 0, 0, 0, 0, 0};
    for (int b = tid; b < EVAL_BLOCKS; b += 256)
        for (int c2 = 0; c2 < 6; c2++) v[c2] += g_part[b * 8 + c2];
    for (int c2 = 0; c2 < 6; c2++) sh[c2][tid] = v[c2];
    __syncthreads();
    for (int s = 128; s > 0; s >>= 1) {
        if (tid < s)
            for (int c2 = 0; c2 < 6; c2++) sh[c2][tid] += sh[c2][tid + s];
        __syncthreads();
    }
    if (tid == 0) {
        double S1 = sh[0][0], S2 = sh[1][0], pok = sh[2][0];
        double nok = sh[3][0], sp = sh[4][0], sn = sh[5][0];
        double pw = sn / sp;
        out[0] = (float)(pw * S1 + S2);
        out[1] = (float)pok;
        out[2] = (float)nok;
    }
}

// ---------------- launch ----------------
extern "C" void kernel_launch(void* const* d_in, const int* in_sizes, int n_in,
                              void* d_out, int out_size) {
    const float* thax_table = (const float*)d_in[0];
    const float* sine_table = (const float*)d_in[1];
    const float* rule_W     = (const float*)d_in[2];
    const float* rule_b     = (const float*)d_in[3];
    const float* eval_w     = (const float*)d_in[4];
    const float* eval_b     = (const float*)d_in[5];
    const float* pos_vals   = (const float*)d_in[6];
    const float* neg_vals   = (const float*)d_in[7];
    const int*   init_thax  = (const int*)d_in[8];
    const int*   init_sine  = (const int*)d_in[9];
    const int*   parents    = (const int*)d_in[10];
    const int*   rules      = (const int*)d_in[11];

    (void)in_sizes; (void)n_in; (void)out_size;

    k_init<<<(NINIT * 32 + 255) / 256, 256>>>(thax_table, sine_table, init_thax, init_sine);
    k_group<<<LVLS, 256>>>(rules);
    for (int l = 0; l < LVLS; l++)
        k_level<<<2 * NRULES, 128>>>(rule_W, rule_b, parents, l);
    k_eval<<<EVAL_BLOCKS, 256>>>(eval_w, eval_b, pos_vals, neg_vals);
    k_final<<<1, 256>>>((float*)d_out);
}